// round 6
// baseline (speedup 1.0000x reference)
#include <cuda_runtime.h>
#include <math.h>

#define BB  8
#define NN  325
#define FIN 32
#define TT  24
#define HH  4
#define CC  32
#define HC  128
#define KMAX 8

// -------- scratch (device globals; no allocation allowed) --------
__device__ float g_Wh  [(size_t)BB * TT * NN * HC];   // [b][t][n][o]  ~32MB
__device__ float g_f1  [(size_t)BB * TT * NN * HH];   // [b][t][n][h]
__device__ float g_f2  [(size_t)BB * TT * NN * HH];
__device__ float g_Sall[(size_t)BB * TT * HC];        // [bt][o]
__device__ int   g_nidx[NN * KMAX];
__device__ float g_nw  [NN * KMAX];
__device__ int   g_ncnt[NN];

// ================= K0: constrain weights + neighbor compaction =================
// One warp per row i. Deterministic (ballot-ordered, j ascending).
__global__ void k0_neighbors(const float* __restrict__ iw,
                             const float* __restrict__ base,
                             const float* __restrict__ mask) {
    int i    = blockIdx.x;
    int lane = threadIdx.x;
    __shared__ int   s_idx[KMAX];
    __shared__ float s_val[KMAX];

    float s   = 0.f;
    int   cnt = 0;
    for (int jb = 0; jb < NN; jb += 32) {
        int j = jb + lane;
        float m = 0.f, mv = 0.f;
        if (j < NN) {
            m = mask[i * NN + j];
            float w  = iw  [i * NN + j];
            float bb = base[i * NN + j];
            float v = fminf(fmaxf(w, 0.5f * bb), 1.5f * bb);
            v = fmaxf(v, 0.f);
            mv = v * m;
        }
        s += mv;
        unsigned bal = __ballot_sync(0xffffffffu, m != 0.f);
        if (m != 0.f) {
            int pos = cnt + __popc(bal & ((1u << lane) - 1u));
            if (pos < KMAX) { s_idx[pos] = j; s_val[pos] = mv; }
        }
        cnt += __popc(bal);
    }
    #pragma unroll
    for (int off = 16; off; off >>= 1) s += __shfl_xor_sync(0xffffffffu, s, off);
    if (s == 0.f) s = 1e-6f;
    __syncwarp();

    cnt = min(cnt, KMAX);
    if (lane == 0) g_ncnt[i] = cnt;
    if (lane < cnt) {
        g_nidx[i * KMAX + lane] = s_idx[lane];
        g_nw  [i * KMAX + lane] = s_val[lane] / s;
    }
}

// ================= K1: Wh = xp @ W^T + b, fused f1/f2 =================
// Block = (b, n); 128 threads = output feature o. x staged in smem (broadcast
// LDS.128 along t), W row in registers. 768 FFMA/thread.
__global__ void __launch_bounds__(HC) k1_wh(const float* __restrict__ x,
                                            const float* __restrict__ Ww,
                                            const float* __restrict__ Wb,
                                            const float* __restrict__ attn) {
    int blk = blockIdx.x;
    int b = blk / NN, n = blk % NN;
    int o = threadIdx.x;             // 0..127
    int h = o >> 5, c = o & 31;

    __shared__ __align__(16) float x_sm[FIN * TT];   // [f][t], rows 96B-aligned
    __shared__ float W_sm[HC * 33];                  // padded: bank-conflict-free

    const float* xb = x + ((size_t)b * NN + n) * (FIN * TT);
    for (int idx = o; idx < FIN * TT; idx += HC) x_sm[idx] = xb[idx];
    for (int idx = o; idx < HC * FIN; idx += HC) {
        int oo = idx >> 5, ff = idx & 31;
        W_sm[oo * 33 + ff] = Ww[idx];
    }
    __syncthreads();

    float wreg[FIN];
    #pragma unroll
    for (int f = 0; f < FIN; f++) wreg[f] = W_sm[o * 33 + f];
    float bias = Wb[o];

    float acc[TT];
    #pragma unroll
    for (int t = 0; t < TT; t++) acc[t] = bias;

    #pragma unroll
    for (int f = 0; f < FIN; f++) {
        float wv = wreg[f];
        const float4* xr = (const float4*)&x_sm[f * TT];
        #pragma unroll
        for (int q = 0; q < TT / 4; q++) {
            float4 v = xr[q];
            acc[q*4+0] = fmaf(v.x, wv, acc[q*4+0]);
            acc[q*4+1] = fmaf(v.y, wv, acc[q*4+1]);
            acc[q*4+2] = fmaf(v.z, wv, acc[q*4+2]);
            acc[q*4+3] = fmaf(v.w, wv, acc[q*4+3]);
        }
    }

    float a1 = attn[h * (2 * CC) + c];
    float a2 = attn[h * (2 * CC) + CC + c];

    #pragma unroll
    for (int t = 0; t < TT; t++) {
        size_t wbase = ((size_t)(b * TT + t) * NN + n) * HC;
        g_Wh[wbase + o] = acc[t];
        float v1 = acc[t] * a1;
        float v2 = acc[t] * a2;
        #pragma unroll
        for (int off = 16; off; off >>= 1) {
            v1 += __shfl_xor_sync(0xffffffffu, v1, off);
            v2 += __shfl_xor_sync(0xffffffffu, v2, off);
        }
        if (c == 0) {
            size_t fb = ((size_t)(b * TT + t) * NN + n) * HH + h;
            g_f1[fb] = v1;
            g_f2[fb] = v2;
        }
    }
}

// ================= K2: S_all[bt][o] = sum_n Wh[bt][n][o] =================
__global__ void __launch_bounds__(HC) k2_colsum() {
    int bt = blockIdx.x;
    int o  = threadIdx.x;
    const float* base = g_Wh + (size_t)bt * NN * HC + o;
    float a0 = 0.f, a1 = 0.f, a2 = 0.f, a3 = 0.f, a4 = 0.f;
    #pragma unroll 1
    for (int n = 0; n < NN; n += 5) {   // 325 = 5 * 65, MLP = 5
        a0 += base[(size_t)(n + 0) * HC];
        a1 += base[(size_t)(n + 1) * HC];
        a2 += base[(size_t)(n + 2) * HC];
        a3 += base[(size_t)(n + 3) * HC];
        a4 += base[(size_t)(n + 4) * HC];
    }
    g_Sall[(size_t)bt * HC + o] = ((a0 + a1) + (a2 + a3)) + a4;
}

// ================= K3: sparse softmax + weighted sum + transpose =================
// Block = (b, i); 128 threads = o. Loops over t; results staged in smem and
// written coalesced as out[b][i][o][t].
__global__ void __launch_bounds__(HC) k3_out(float* __restrict__ out) {
    int blk = blockIdx.x;
    int b = blk / NN, i = blk % NN;
    int o = threadIdx.x;
    int h = o >> 5;

    __shared__ float o_sm[HC * (TT + 1)];   // pad to 25 -> conflict-free

    int cnt = g_ncnt[i];
    int   jidx[KMAX];
    float jw[KMAX];
    #pragma unroll
    for (int k = 0; k < KMAX; k++) {
        jidx[k] = (k < cnt) ? g_nidx[i * KMAX + k] : 0;
        jw[k]   = (k < cnt) ? g_nw  [i * KMAX + k] : 0.f;
    }

    for (int t = 0; t < TT; t++) {
        int bt = b * TT + t;
        float f1i = g_f1[((size_t)bt * NN + i) * HH + h];

        float sarr[KMAX];
        float m = 0.f;   // max over {0, scores}: non-neighbor scores are exactly 0
        #pragma unroll
        for (int k = 0; k < KMAX; k++) {
            if (k < cnt) {
                float f2v = g_f2[((size_t)bt * NN + jidx[k]) * HH + h];
                float e = f1i + f2v;
                float lr = (e > 0.f) ? e : 0.2f * e;   // leaky_relu, slope 0.2
                sarr[k] = lr + jw[k];
                m = fmaxf(m, sarr[k]);
            }
        }
        float E0    = expf(-m);
        float denom = (float)(NN - cnt) * E0;
        float acc   = E0 * g_Sall[(size_t)bt * HC + o];
        #pragma unroll
        for (int k = 0; k < KMAX; k++) {
            if (k < cnt) {
                float Ek = expf(sarr[k] - m);
                denom += Ek;
                acc += (Ek - E0) * g_Wh[((size_t)bt * NN + jidx[k]) * HC + o];
            }
        }
        o_sm[o * (TT + 1) + t] = acc / denom;
    }
    __syncthreads();

    float* ob = out + ((size_t)b * NN + i) * (HC * TT);
    for (int idx = o; idx < HC * TT; idx += HC) {
        int oo = idx / TT, tt = idx - oo * TT;
        ob[idx] = o_sm[oo * (TT + 1) + tt];
    }
}

// ================= launch =================
extern "C" void kernel_launch(void* const* d_in, const int* in_sizes, int n_in,
                              void* d_out, int out_size) {
    const float* x    = (const float*)d_in[0];  // (B, N, F_IN, T)
    const float* Ww   = (const float*)d_in[1];  // (HC, F_IN)
    const float* Wb   = (const float*)d_in[2];  // (HC,)
    const float* attn = (const float*)d_in[3];  // (H, 2C)
    const float* iw   = (const float*)d_in[4];  // (N, N)
    const float* base = (const float*)d_in[5];  // (N, N)
    const float* mask = (const float*)d_in[6];  // (N, N)
    float* out = (float*)d_out;                 // (B, N, HC, T)
    (void)in_sizes; (void)n_in; (void)out_size;

    k0_neighbors<<<NN, 32>>>(iw, base, mask);
    k1_wh<<<BB * NN, HC>>>(x, Ww, Wb, attn);
    k2_colsum<<<BB * TT, HC>>>();
    k3_out<<<BB * NN, HC>>>(out);
}

// round 7
// speedup vs baseline: 1.0002x; 1.0002x over previous
#include <cuda_runtime.h>
#include <math.h>

#define BB  8
#define NN  325
#define FIN 32
#define TT  24
#define HH  4
#define CC  32
#define HC  128
#define KMAX 8

// -------- scratch (device globals; no allocation allowed) --------
__device__ float g_Wh  [(size_t)BB * TT * NN * HC];   // [b][t][n][o]  ~32MB
__device__ float g_f1  [(size_t)BB * TT * NN * HH];   // [b][t][n][h]
__device__ float g_f2  [(size_t)BB * TT * NN * HH];
__device__ float g_Sall[(size_t)BB * TT * HC];        // [bt][o]
__device__ int   g_nidx[NN * KMAX];
__device__ float g_nw  [NN * KMAX];
__device__ int   g_ncnt[NN];

// ================= K0: constrain weights + neighbor compaction =================
// One warp per row i. Deterministic (ballot-ordered, j ascending).
__global__ void k0_neighbors(const float* __restrict__ iw,
                             const float* __restrict__ base,
                             const float* __restrict__ mask) {
    int i    = blockIdx.x;
    int lane = threadIdx.x;
    __shared__ int   s_idx[KMAX];
    __shared__ float s_val[KMAX];

    float s   = 0.f;
    int   cnt = 0;
    for (int jb = 0; jb < NN; jb += 32) {
        int j = jb + lane;
        float m = 0.f, mv = 0.f;
        if (j < NN) {
            m = mask[i * NN + j];
            float w  = iw  [i * NN + j];
            float bb = base[i * NN + j];
            float v = fminf(fmaxf(w, 0.5f * bb), 1.5f * bb);
            v = fmaxf(v, 0.f);
            mv = v * m;
        }
        s += mv;
        unsigned bal = __ballot_sync(0xffffffffu, m != 0.f);
        if (m != 0.f) {
            int pos = cnt + __popc(bal & ((1u << lane) - 1u));
            if (pos < KMAX) { s_idx[pos] = j; s_val[pos] = mv; }
        }
        cnt += __popc(bal);
    }
    #pragma unroll
    for (int off = 16; off; off >>= 1) s += __shfl_xor_sync(0xffffffffu, s, off);
    if (s == 0.f) s = 1e-6f;
    __syncwarp();

    cnt = min(cnt, KMAX);
    if (lane == 0) g_ncnt[i] = cnt;
    if (lane < cnt) {
        g_nidx[i * KMAX + lane] = s_idx[lane];
        g_nw  [i * KMAX + lane] = s_val[lane] / s;
    }
}

// ================= K1: Wh = xp @ W^T + b, fused f1/f2 =================
// Block = (b, n); 128 threads = output feature o. x staged in smem (broadcast
// LDS.128 along t), W row in registers. 768 FFMA/thread.
__global__ void __launch_bounds__(HC) k1_wh(const float* __restrict__ x,
                                            const float* __restrict__ Ww,
                                            const float* __restrict__ Wb,
                                            const float* __restrict__ attn) {
    int blk = blockIdx.x;
    int b = blk / NN, n = blk % NN;
    int o = threadIdx.x;             // 0..127
    int h = o >> 5, c = o & 31;

    __shared__ __align__(16) float x_sm[FIN * TT];   // [f][t], rows 96B-aligned
    __shared__ float W_sm[HC * 33];                  // padded: bank-conflict-free

    const float* xb = x + ((size_t)b * NN + n) * (FIN * TT);
    for (int idx = o; idx < FIN * TT; idx += HC) x_sm[idx] = xb[idx];
    for (int idx = o; idx < HC * FIN; idx += HC) {
        int oo = idx >> 5, ff = idx & 31;
        W_sm[oo * 33 + ff] = Ww[idx];
    }
    __syncthreads();

    float wreg[FIN];
    #pragma unroll
    for (int f = 0; f < FIN; f++) wreg[f] = W_sm[o * 33 + f];
    float bias = Wb[o];

    float acc[TT];
    #pragma unroll
    for (int t = 0; t < TT; t++) acc[t] = bias;

    #pragma unroll
    for (int f = 0; f < FIN; f++) {
        float wv = wreg[f];
        const float4* xr = (const float4*)&x_sm[f * TT];
        #pragma unroll
        for (int q = 0; q < TT / 4; q++) {
            float4 v = xr[q];
            acc[q*4+0] = fmaf(v.x, wv, acc[q*4+0]);
            acc[q*4+1] = fmaf(v.y, wv, acc[q*4+1]);
            acc[q*4+2] = fmaf(v.z, wv, acc[q*4+2]);
            acc[q*4+3] = fmaf(v.w, wv, acc[q*4+3]);
        }
    }

    float a1 = attn[h * (2 * CC) + c];
    float a2 = attn[h * (2 * CC) + CC + c];

    #pragma unroll
    for (int t = 0; t < TT; t++) {
        size_t wbase = ((size_t)(b * TT + t) * NN + n) * HC;
        g_Wh[wbase + o] = acc[t];
        float v1 = acc[t] * a1;
        float v2 = acc[t] * a2;
        #pragma unroll
        for (int off = 16; off; off >>= 1) {
            v1 += __shfl_xor_sync(0xffffffffu, v1, off);
            v2 += __shfl_xor_sync(0xffffffffu, v2, off);
        }
        if (c == 0) {
            size_t fb = ((size_t)(b * TT + t) * NN + n) * HH + h;
            g_f1[fb] = v1;
            g_f2[fb] = v2;
        }
    }
}

// ================= K2: S_all[bt][o] = sum_n Wh[bt][n][o] =================
__global__ void __launch_bounds__(HC) k2_colsum() {
    int bt = blockIdx.x;
    int o  = threadIdx.x;
    const float* base = g_Wh + (size_t)bt * NN * HC + o;
    float a0 = 0.f, a1 = 0.f, a2 = 0.f, a3 = 0.f, a4 = 0.f;
    #pragma unroll 1
    for (int n = 0; n < NN; n += 5) {   // 325 = 5 * 65, MLP = 5
        a0 += base[(size_t)(n + 0) * HC];
        a1 += base[(size_t)(n + 1) * HC];
        a2 += base[(size_t)(n + 2) * HC];
        a3 += base[(size_t)(n + 3) * HC];
        a4 += base[(size_t)(n + 4) * HC];
    }
    g_Sall[(size_t)bt * HC + o] = ((a0 + a1) + (a2 + a3)) + a4;
}

// ================= K3: sparse softmax + weighted sum + transpose =================
// Block = (b, i); 128 threads = o. Loops over t; results staged in smem and
// written coalesced as out[b][i][o][t].
__global__ void __launch_bounds__(HC) k3_out(float* __restrict__ out) {
    int blk = blockIdx.x;
    int b = blk / NN, i = blk % NN;
    int o = threadIdx.x;
    int h = o >> 5;

    __shared__ float o_sm[HC * (TT + 1)];   // pad to 25 -> conflict-free

    int cnt = g_ncnt[i];
    int   jidx[KMAX];
    float jw[KMAX];
    #pragma unroll
    for (int k = 0; k < KMAX; k++) {
        jidx[k] = (k < cnt) ? g_nidx[i * KMAX + k] : 0;
        jw[k]   = (k < cnt) ? g_nw  [i * KMAX + k] : 0.f;
    }

    for (int t = 0; t < TT; t++) {
        int bt = b * TT + t;
        float f1i = g_f1[((size_t)bt * NN + i) * HH + h];

        float sarr[KMAX];
        float m = 0.f;   // max over {0, scores}: non-neighbor scores are exactly 0
        #pragma unroll
        for (int k = 0; k < KMAX; k++) {
            if (k < cnt) {
                float f2v = g_f2[((size_t)bt * NN + jidx[k]) * HH + h];
                float e = f1i + f2v;
                float lr = (e > 0.f) ? e : 0.2f * e;   // leaky_relu, slope 0.2
                sarr[k] = lr + jw[k];
                m = fmaxf(m, sarr[k]);
            }
        }
        float E0    = expf(-m);
        float denom = (float)(NN - cnt) * E0;
        float acc   = E0 * g_Sall[(size_t)bt * HC + o];
        #pragma unroll
        for (int k = 0; k < KMAX; k++) {
            if (k < cnt) {
                float Ek = expf(sarr[k] - m);
                denom += Ek;
                acc += (Ek - E0) * g_Wh[((size_t)bt * NN + jidx[k]) * HC + o];
            }
        }
        o_sm[o * (TT + 1) + t] = acc / denom;
    }
    __syncthreads();

    float* ob = out + ((size_t)b * NN + i) * (HC * TT);
    for (int idx = o; idx < HC * TT; idx += HC) {
        int oo = idx / TT, tt = idx - oo * TT;
        ob[idx] = o_sm[oo * (TT + 1) + tt];
    }
}

// ================= launch =================
extern "C" void kernel_launch(void* const* d_in, const int* in_sizes, int n_in,
                              void* d_out, int out_size) {
    const float* x    = (const float*)d_in[0];  // (B, N, F_IN, T)
    const float* Ww   = (const float*)d_in[1];  // (HC, F_IN)
    const float* Wb   = (const float*)d_in[2];  // (HC,)
    const float* attn = (const float*)d_in[3];  // (H, 2C)
    const float* iw   = (const float*)d_in[4];  // (N, N)
    const float* base = (const float*)d_in[5];  // (N, N)
    const float* mask = (const float*)d_in[6];  // (N, N)
    float* out = (float*)d_out;                 // (B, N, HC, T)
    (void)in_sizes; (void)n_in; (void)out_size;

    k0_neighbors<<<NN, 32>>>(iw, base, mask);
    k1_wh<<<BB * NN, HC>>>(x, Ww, Wb, attn);
    k2_colsum<<<BB * TT, HC>>>();
    k3_out<<<BB * NN, HC>>>(out);
}